// round 6
// baseline (speedup 1.0000x reference)
#include <cuda_runtime.h>
#include <cuda_bf16.h>
#include <cstdint>

#define NG   32
#define NPG  1024
#define NN   (NG*NPG)
#define HD   128
#define NLAY 4
#define NPAR 256
#define NPT  (NG*NPAR)
#define NCLS 50
#define DCCN 16
#define CS   (DCCN*NCLS)   // 800

typedef unsigned long long u64t;

__device__ __forceinline__ u64t pk2(float x, float y){ u64t r; asm("mov.b64 %0, {%1,%2};" : "=l"(r) : "f"(x), "f"(y)); return r; }
__device__ __forceinline__ void upk2(u64t p, float& x, float& y){ asm("mov.b64 {%0,%1}, %2;" : "=f"(x), "=f"(y) : "l"(p)); }
__device__ __forceinline__ u64t fma2_(u64t a, u64t b, u64t c){ u64t d; asm("fma.rn.f32x2 %0, %1, %2, %3;" : "=l"(d) : "l"(a), "l"(b), "l"(c)); return d; }
__device__ __forceinline__ u64t mul2_(u64t a, u64t b){ u64t d; asm("mul.rn.f32x2 %0, %1, %2;" : "=l"(d) : "l"(a), "l"(b)); return d; }
__device__ __forceinline__ u64t add2_(u64t a, u64t b){ u64t d; asm("add.rn.f32x2 %0, %1, %2;" : "=l"(d) : "l"(a), "l"(b)); return d; }

// ---------------- device scratch ----------------
__device__ __align__(256) float g_h0[NN*HD];
__device__ __align__(256) float g_f0[NN*HD];
__device__ __align__(256) float g_f1[NN*HD];
__device__ __align__(256) float g_f2[NN*HD];
__device__ __align__(256) float g_f3[NN*HD];
__device__ __align__(256) float g_l2[NN];
__device__ __align__(256) float g_u [NG*1024*4];
__device__ __align__(256) float g_Vc[NG*1024*4];
__device__ __align__(256) float g_m [NG*1024];   // NEGATED row max
__device__ __align__(256) float g_iZ[NG*1024];
__device__ __align__(256) float g_SC[NG*1024*4];
__device__ __align__(256) float g_delta[NN*NCLS];
__device__ __align__(256) float g_gamma[NN*NCLS];
__device__ __align__(256) float g_zs[NG*CS];
__device__ __align__(256) float g_z [NG*CS];

__device__ __forceinline__ float* featptr(int l){
    switch(l){ case 0: return g_f0; case 1: return g_f1; case 2: return g_f2; default: return g_f3; }
}

// ---------------- embedding + leaf l2 (leaf features stay in g_h0) ----------------
__global__ void k_embed(const int* __restrict__ type_ids, const int* __restrict__ token_ids,
                        const float* __restrict__ temb, const float* __restrict__ kemb){
    int idx = blockIdx.x*256 + threadIdx.x;          // n*32 + q  (warp == one node)
    int n = idx >> 5, q = idx & 31;
    float4 v;
    if (q < 16) v = *(const float4*)(temb + (size_t)type_ids[n]*64 + q*4);
    else        v = *(const float4*)(kemb + (size_t)token_ids[n]*64 + (q-16)*4);
    size_t o = (size_t)n*HD + q*4;
    *(float4*)(g_h0 + o) = v;
    bool leaf = (n & (NPG-1)) >= NPAR;
    float sq = v.x*v.x + v.y*v.y + v.z*v.z + v.w*v.w;
    #pragma unroll
    for (int s=16;s;s>>=1) sq += __shfl_xor_sync(0xffffffffu, sq, s);
    if (q == 0) g_l2[n] = leaf ? 4.f*sq : 0.f;
}

// ---------------- fused gather + GEMM + bias/relu + l2 ----------------
// 32-row tiles (grid 256). Column-pair packed accumulators: B float4 == 2 f32x2 packs free.
__global__ __launch_bounds__(256) void k_gemm(const float* __restrict__ WLp,
        const float* __restrict__ WRp, const float* __restrict__ WTp,
        const float* __restrict__ bconv,
        const float* __restrict__ lw, const float* __restrict__ rw, int layer){
    __shared__ __align__(16) float GLx[16][34];
    __shared__ __align__(16) float GRx[16][34];
    __shared__ __align__(16) float Xs [16][34];
    __shared__ __align__(16) float Ws3[3][16][128];
    __shared__ float lw_s[128], rw_s[128];
    const int tid = threadIdx.x;
    const int row0 = blockIdx.x*32;                  // parent row [0,8192)
    const int g = row0 >> 8, l0 = row0 & 255;
    const float* hin = (layer==0) ? g_h0 : featptr(layer-1);
    const float* Wb[3] = { WLp + layer*HD*HD, WRp + layer*HD*HD, WTp + layer*HD*HD };
    const int rg = tid >> 4;                         // 0..15 : rows rg*2, rg*2+1
    const int cg = tid & 15;                         // 0..15 : cols cg*8..+7

    if (tid < 128){
        int e_local = 4*l0 + tid;
        bool valid = e_local < 1023;
        lw_s[tid] = valid ? lw[g*1023 + e_local] : 0.f;
        rw_s[tid] = valid ? rw[g*1023 + e_local] : 0.f;
    }

    u64t acc[2][4];                                  // [row][colpair]
    #pragma unroll
    for (int r=0;r<2;r++){ acc[r][0]=0; acc[r][1]=0; acc[r][2]=0; acc[r][3]=0; }

    const int p_rel = tid >> 2, q = tid & 3;         // staging threads (tid<128)
    for (int k0 = 0; k0 < HD; k0 += 16){
        __syncthreads();
        if (tid < 128){
            // parent tile
            float4 v = *(const float4*)(hin + (size_t)(g*NPG + l0 + p_rel)*HD + k0 + q*4);
            Xs[q*4+0][p_rel]=v.x; Xs[q*4+1][p_rel]=v.y; Xs[q*4+2][p_rel]=v.z; Xs[q*4+3][p_rel]=v.w;
            // gathered child tiles (children >=256 are leaves: read h0)
            float glx=0,gly=0,glz=0,glw=0, grx=0,gry=0,grz=0,grw=0;
            #pragma unroll
            for (int j=0;j<4;j++){
                float wl = lw_s[p_rel*4+j], wr = rw_s[p_rel*4+j];
                int c_local = 4*(l0+p_rel) + 1 + j;
                if (c_local > 1023) c_local = 1023;  // weight already 0
                const float* csrc = (c_local < NPAR) ? hin : g_h0;
                float4 cv = *(const float4*)(csrc + (size_t)(g*NPG + c_local)*HD + k0 + q*4);
                glx += wl*cv.x; gly += wl*cv.y; glz += wl*cv.z; glw += wl*cv.w;
                grx += wr*cv.x; gry += wr*cv.y; grz += wr*cv.z; grw += wr*cv.w;
            }
            GLx[q*4+0][p_rel]=glx; GLx[q*4+1][p_rel]=gly; GLx[q*4+2][p_rel]=glz; GLx[q*4+3][p_rel]=glw;
            GRx[q*4+0][p_rel]=grx; GRx[q*4+1][p_rel]=gry; GRx[q*4+2][p_rel]=grz; GRx[q*4+3][p_rel]=grw;
        }
        // weight chunks for all 3 segments (all 256 threads)
        #pragma unroll
        for (int i=0;i<6;i++){
            int qq = tid + i*256;                    // 0..1535
            int seg = qq >> 9, r = qq & 511;
            int k = r >> 5, n4 = r & 31;
            *(float4*)&Ws3[seg][k][n4*4] = *(const float4*)(Wb[seg] + (size_t)(k0+k)*HD + n4*4);
        }
        __syncthreads();
        #pragma unroll 4
        for (int k=0;k<16;k++){
            #pragma unroll
            for (int seg=0;seg<3;seg++){
                const float* As = (seg==0) ? &GLx[k][0] : (seg==1) ? &GRx[k][0] : &Xs[k][0];
                float a0 = As[rg*2], a1 = As[rg*2+1];
                u64t A0 = pk2(a0,a0), A1 = pk2(a1,a1);
                ulonglong2 w0 = *(const ulonglong2*)&Ws3[seg][k][cg*8];
                ulonglong2 w1 = *(const ulonglong2*)&Ws3[seg][k][cg*8+4];
                acc[0][0] = fma2_(A0, w0.x, acc[0][0]);
                acc[0][1] = fma2_(A0, w0.y, acc[0][1]);
                acc[0][2] = fma2_(A0, w1.x, acc[0][2]);
                acc[0][3] = fma2_(A0, w1.y, acc[0][3]);
                acc[1][0] = fma2_(A1, w0.x, acc[1][0]);
                acc[1][1] = fma2_(A1, w0.y, acc[1][1]);
                acc[1][2] = fma2_(A1, w1.x, acc[1][2]);
                acc[1][3] = fma2_(A1, w1.y, acc[1][3]);
            }
        }
    }
    // epilogue
    float* fo = featptr(layer);
    float b8[8];
    *(float4*)&b8[0] = *(const float4*)(bconv + layer*HD + cg*8);
    *(float4*)&b8[4] = *(const float4*)(bconv + layer*HD + cg*8 + 4);
    float sqr[2];
    #pragma unroll
    for (int r=0;r<2;r++){
        float v[8];
        #pragma unroll
        for (int cp=0;cp<4;cp++) upk2(acc[r][cp], v[cp*2], v[cp*2+1]);
        float sq = 0.f;
        #pragma unroll
        for (int c=0;c<8;c++){ v[c] = fmaxf(v[c]+b8[c], 0.f); sq += v[c]*v[c]; }
        sqr[r] = sq;
        int loc = l0 + rg*2 + r;
        float4 o0 = {v[0],v[1],v[2],v[3]};
        float4 o1 = {v[4],v[5],v[6],v[7]};
        *(float4*)(fo + (size_t)(g*NPG + loc)*HD + cg*8    ) = o0;
        *(float4*)(fo + (size_t)(g*NPG + loc)*HD + cg*8 + 4) = o1;
    }
    #pragma unroll
    for (int o=8;o;o>>=1){ sqr[0] += __shfl_xor_sync(0xffffffffu, sqr[0], o);
                           sqr[1] += __shfl_xor_sync(0xffffffffu, sqr[1], o); }
    if (cg == 0){
        atomicAdd(&g_l2[g*NPG + l0 + rg*2    ], sqr[0]);
        atomicAdd(&g_l2[g*NPG + l0 + rg*2 + 1], sqr[1]);
    }
}

// ---------------- top-8 per graph + gather u, init Vcum ----------------
__global__ __launch_bounds__(1024) void k_top(){
    __shared__ float l2s[1024];
    __shared__ float rv[32]; __shared__ int ri[32];
    __shared__ int top8[8];
    int g = blockIdx.x, tid = threadIdx.x;
    int lane = tid & 31, warp = tid >> 5;
    l2s[tid] = g_l2[g*1024 + tid];
    __syncthreads();
    for (int t=0;t<8;t++){
        float v = l2s[tid]; int idx = tid;
        #pragma unroll
        for (int o=16;o;o>>=1){
            float v2 = __shfl_xor_sync(0xffffffffu, v, o);
            int   i2 = __shfl_xor_sync(0xffffffffu, idx, o);
            if (v2 > v || (v2 == v && i2 < idx)){ v = v2; idx = i2; }
        }
        if (lane == 0){ rv[warp] = v; ri[warp] = idx; }
        __syncthreads();
        if (warp == 0){
            float vv = rv[lane]; int ii = ri[lane];
            #pragma unroll
            for (int o=16;o;o>>=1){
                float v2 = __shfl_xor_sync(0xffffffffu, vv, o);
                int   i2 = __shfl_xor_sync(0xffffffffu, ii, o);
                if (v2 > vv || (v2 == vv && i2 < ii)){ vv = v2; ii = i2; }
            }
            if (lane == 0){ top8[t] = ii; l2s[ii] = -1e30f; }
        }
        __syncthreads();
    }
    int bcap = tid >> 7, hh = tid & 127;
    int node = top8[bcap];
    size_t nb = (size_t)(g*NPG + node)*HD + hh;
    float4 uv;
    if (node < NPAR){
        uv.x = g_f0[nb]; uv.y = g_f1[nb]; uv.z = g_f2[nb]; uv.w = g_f3[nb];
    } else {
        float h = g_h0[nb];
        uv.x = h; uv.y = h; uv.z = h; uv.w = h;
    }
    *(float4*)&g_u [(size_t)(g*1024 + tid)*4] = uv;
    *(float4*)&g_Vc[(size_t)(g*1024 + tid)*4] = uv;
}

// ---------------- VTS phase A: per-row (neg)max + 1/Z, ILP-2 ----------------
__global__ __launch_bounds__(256) void k_phaseA(){
    __shared__ __align__(16) ulonglong2 sVp2[1024];
    int g = blockIdx.x, tid = threadIdx.x;
    int row = blockIdx.y*256 + tid;
    for (int i=tid;i<512;i+=256){
        float4 c0 = *(const float4*)&g_Vc[(size_t)(g*1024 + 2*i  )*4];
        float4 c1 = *(const float4*)&g_Vc[(size_t)(g*1024 + 2*i+1)*4];
        ulonglong2 A, B;
        A.x = pk2(c0.x,c1.x); A.y = pk2(c0.y,c1.y);
        B.x = pk2(c0.z,c1.z); B.y = pk2(c0.w,c1.w);
        sVp2[i*2] = A; sVp2[i*2+1] = B;
    }
    __syncthreads();
    float4 u = *(const float4*)&g_u[(size_t)(g*1024 + row)*4];
    u64t U0 = pk2(u.x,u.x), U1 = pk2(u.y,u.y), U2 = pk2(u.z,u.z), U3 = pk2(u.w,u.w);
    float ma = -1e30f, mb = -1e30f;
    #pragma unroll 2
    for (int jp=0;jp<512;jp+=2){
        ulonglong2 P01 = sVp2[jp*2],   P23 = sVp2[jp*2+1];
        ulonglong2 Q01 = sVp2[jp*2+2], Q23 = sVp2[jp*2+3];
        u64t t = mul2_(U0, P01.x); u64t s = mul2_(U0, Q01.x);
        t = fma2_(U1, P01.y, t);   s = fma2_(U1, Q01.y, s);
        t = fma2_(U2, P23.x, t);   s = fma2_(U2, Q23.x, s);
        t = fma2_(U3, P23.y, t);   s = fma2_(U3, Q23.y, s);
        float t0,t1,s0,s1; upk2(t,t0,t1); upk2(s,s0,s1);
        ma = fmaxf(ma, fmaxf(t0,t1));
        mb = fmaxf(mb, fmaxf(s0,s1));
    }
    float mn = -fmaxf(ma, mb);
    u64t MN = pk2(mn, mn);
    float za = 0.f, zb = 0.f;
    #pragma unroll 2
    for (int jp=0;jp<512;jp+=2){
        ulonglong2 P01 = sVp2[jp*2],   P23 = sVp2[jp*2+1];
        ulonglong2 Q01 = sVp2[jp*2+2], Q23 = sVp2[jp*2+3];
        u64t t = mul2_(U0, P01.x); u64t s = mul2_(U0, Q01.x);
        t = fma2_(U1, P01.y, t);   s = fma2_(U1, Q01.y, s);
        t = fma2_(U2, P23.x, t);   s = fma2_(U2, Q23.x, s);
        t = fma2_(U3, P23.y, t);   s = fma2_(U3, Q23.y, s);
        t = add2_(t, MN);          s = add2_(s, MN);
        float t0,t1,s0,s1; upk2(t,t0,t1); upk2(s,s0,s1);
        za += __expf(t0); za += __expf(t1);
        zb += __expf(s0); zb += __expf(s1);
    }
    g_m [g*1024 + row] = mn;
    g_iZ[g*1024 + row] = 1.f/(za+zb);
}

// ---------------- VTS phase B: v_new = beta^T u, ILP-2 ----------------
__global__ __launch_bounds__(256) void k_phaseB(int last){
    __shared__ __align__(16) ulonglong2 sUp2[1024];
    __shared__ __align__(16) float4 sUn[1024];
    __shared__ u64t sMn2[512];
    __shared__ u64t sZ2[512];
    int g = blockIdx.x, tid = threadIdx.x;
    int col = blockIdx.y*256 + tid;
    for (int i=tid;i<512;i+=256){
        float4 u0 = *(const float4*)&g_u[(size_t)(g*1024 + 2*i  )*4];
        float4 u1 = *(const float4*)&g_u[(size_t)(g*1024 + 2*i+1)*4];
        sUn[2*i] = u0; sUn[2*i+1] = u1;
        ulonglong2 A, B;
        A.x = pk2(u0.x,u1.x); A.y = pk2(u0.y,u1.y);
        B.x = pk2(u0.z,u1.z); B.y = pk2(u0.w,u1.w);
        sUp2[i*2] = A; sUp2[i*2+1] = B;
        sMn2[i] = pk2(g_m [g*1024+2*i], g_m [g*1024+2*i+1]);
        sZ2 [i] = pk2(g_iZ[g*1024+2*i], g_iZ[g*1024+2*i+1]);
    }
    __syncthreads();
    float4 c = *(const float4*)&g_Vc[(size_t)(g*1024 + col)*4];
    u64t C0 = pk2(c.x,c.x), C1 = pk2(c.y,c.y), C2 = pk2(c.z,c.z), C3 = pk2(c.w,c.w);
    u64t a01a = 0, a23a = 0, a01b = 0, a23b = 0;
    #pragma unroll 2
    for (int ip=0;ip<512;ip+=2){
        ulonglong2 P01 = sUp2[ip*2],   P23 = sUp2[ip*2+1];
        ulonglong2 Q01 = sUp2[ip*2+2], Q23 = sUp2[ip*2+3];
        u64t t = mul2_(C0, P01.x);  u64t s2 = mul2_(C0, Q01.x);
        t = fma2_(C1, P01.y, t);    s2 = fma2_(C1, Q01.y, s2);
        t = fma2_(C2, P23.x, t);    s2 = fma2_(C2, Q23.x, s2);
        t = fma2_(C3, P23.y, t);    s2 = fma2_(C3, Q23.y, s2);
        t = add2_(t, sMn2[ip]);     s2 = add2_(s2, sMn2[ip+1]);
        float t0,t1,s0,s1; upk2(t,t0,t1); upk2(s2,s0,s1);
        float e0 = __expf(t0), e1 = __expf(t1);
        float f0 = __expf(s0), f1 = __expf(s1);
        u64t wza = mul2_(pk2(e0,e1), sZ2[ip]);
        u64t wzb = mul2_(pk2(f0,f1), sZ2[ip+1]);
        float w0,w1,x0,x1; upk2(wza,w0,w1); upk2(wzb,x0,x1);
        u64t W0 = pk2(w0,w0), W1 = pk2(w1,w1);
        u64t X0 = pk2(x0,x0), X1 = pk2(x1,x1);
        ulonglong2 Ua = *(const ulonglong2*)&sUn[2*ip];
        ulonglong2 Ub = *(const ulonglong2*)&sUn[2*ip+1];
        ulonglong2 Uc = *(const ulonglong2*)&sUn[2*ip+2];
        ulonglong2 Ud = *(const ulonglong2*)&sUn[2*ip+3];
        a01a = fma2_(W0, Ua.x, a01a); a23a = fma2_(W0, Ua.y, a23a);
        a01a = fma2_(W1, Ub.x, a01a); a23a = fma2_(W1, Ub.y, a23a);
        a01b = fma2_(X0, Uc.x, a01b); a23b = fma2_(X0, Uc.y, a23b);
        a01b = fma2_(X1, Ud.x, a01b); a23b = fma2_(X1, Ud.y, a23b);
    }
    u64t a01 = add2_(a01a, a01b), a23 = add2_(a23a, a23b);
    float a0,a1,a2,a3;
    upk2(a01, a0, a1); upk2(a23, a2, a3);
    if (!last){
        float4 o; o.x=c.x+a0; o.y=c.y+a1; o.z=c.z+a2; o.w=c.w+a3;
        *(float4*)&g_Vc[(size_t)(g*1024 + col)*4] = o;
    } else {
        float sq = a0*a0 + a1*a1 + a2*a2 + a3*a3;
        float sc = sq/(1.f+sq)/(sqrtf(sq + 1e-10f) + 1e-8f);
        float4 o; o.x=a0*sc; o.y=a1*sc; o.z=a2*sc; o.w=a3*sc;
        *(float4*)&g_SC[(size_t)(g*1024 + col)*4] = o;
    }
}

// ---------------- zsum[b,c,s] = sum_{n,m} Wjm[n,c,s,m] * gamma[b,n,s]*SC[b,n,m] ----------------
__global__ __launch_bounds__(512) void k_zsum2(const float* __restrict__ Wjm, int round0){
    __shared__ __align__(16) float4 Ws4[64*16];   // [n][c]
    __shared__ __align__(16) float4 Xs4[64*32];   // [n][b]
    int s = blockIdx.x;
    int n0 = blockIdx.y*64;
    int tid = threadIdx.x;
    const float4* W4 = (const float4*)Wjm;
    #pragma unroll
    for (int i = tid; i < 1024; i += 512){
        int n = i >> 4, c = i & 15;
        Ws4[i] = W4[(size_t)(n0+n)*800 + c*50 + s];
    }
    #pragma unroll
    for (int i = tid; i < 2048; i += 512){
        int n = i >> 5, b = i & 31;
        float ga = round0 ? 0.02f : g_gamma[(size_t)(b*1024 + n0 + n)*50 + s];
        float4 sc = *(const float4*)&g_SC[(size_t)(b*1024 + n0 + n)*4];
        float4 x; x.x = ga*sc.x; x.y = ga*sc.y; x.z = ga*sc.z; x.w = ga*sc.w;
        Xs4[n*32 + b] = x;
    }
    __syncthreads();
    int c = tid & 15, b = tid >> 4;
    float acc = 0.f;
    #pragma unroll 8
    for (int n = 0; n < 64; n++){
        float4 w = Ws4[n*16 + c];
        float4 x = Xs4[n*32 + b];
        acc += w.x*x.x + w.y*x.y + w.z*x.z + w.w*x.w;
    }
    atomicAdd(&g_zs[b*CS + c*NCLS + s], acc);
}

// ---------------- z = squash_c(zsum); re-zero zs for next round ----------------
__global__ void k_zfin(){
    int b = blockIdx.x, s = threadIdx.x;
    if (s >= NCLS) return;
    float vals[DCCN]; float sq = 0.f;
    #pragma unroll
    for (int c=0;c<DCCN;c++){
        float v = g_zs[b*CS + c*NCLS + s]; vals[c]=v; sq += v*v;
        g_zs[b*CS + c*NCLS + s] = 0.f;
    }
    float sc = sq/(1.f+sq)/(sqrtf(sq + 1e-10f) + 1e-8f);
    #pragma unroll
    for (int c=0;c<DCCN;c++) g_z[b*CS + c*NCLS + s] = vals[c]*sc;
}

// ---------------- fused: delta update + gamma = softmax_s(delta) ----------------
__global__ __launch_bounds__(512) void k_dg(const float* __restrict__ Wjm, int accum){
    __shared__ __align__(16) float4 Ws4[800];
    __shared__ float sdel[1600];
    __shared__ float smx[32], siz[32];
    int n = blockIdx.x;
    int tid = threadIdx.x;
    const float4* W4 = (const float4*)Wjm + (size_t)n*800;
    for (int i = tid; i < 800; i += 512) Ws4[i] = W4[i];
    __syncthreads();
    for (int p = tid; p < 1600; p += 512){
        int b = p / 50, s = p % 50;
        float tx=0.f, ty=0.f, tz=0.f, tw=0.f;
        #pragma unroll
        for (int c = 0; c < 16; c++){
            float zv = g_z[b*CS + c*NCLS + s];
            float4 w = Ws4[c*50 + s];
            tx += w.x*zv; ty += w.y*zv; tz += w.z*zv; tw += w.w*zv;
        }
        float4 sc = *(const float4*)&g_SC[(size_t)(b*1024 + n)*4];
        float d = tx*sc.x + ty*sc.y + tz*sc.z + tw*sc.w;
        size_t o = (size_t)(b*1024 + n)*50 + s;
        if (accum) d += g_delta[o];
        g_delta[o] = d;
        sdel[p] = d;
    }
    __syncthreads();
    if (tid < 32){
        float m = -1e30f;
        for (int k=0;k<NCLS;k++) m = fmaxf(m, sdel[tid*50 + k]);
        float Z = 0.f;
        for (int k=0;k<NCLS;k++) Z += __expf(sdel[tid*50 + k] - m);
        smx[tid] = m; siz[tid] = 1.f/Z;
    }
    __syncthreads();
    for (int p = tid; p < 1600; p += 512){
        int b = p / 50;
        size_t o = (size_t)(b*1024 + n)*50 + (p % 50);
        g_gamma[o] = __expf(sdel[p] - smx[b]) * siz[b];
    }
}

// ---------------- logits ----------------
__global__ void k_logit(float* __restrict__ out){
    int b = blockIdx.x, s = threadIdx.x;
    if (s >= NCLS) return;
    float sq = 0.f;
    #pragma unroll
    for (int c=0;c<DCCN;c++){ float v = g_z[b*CS + c*NCLS + s]; sq += v*v; }
    float lg = sqrtf(sq + 1e-10f);
    out[b*NCLS + s] = lg;
    out[NG*NCLS + b*NCLS + s] = lg;
}

// ---------------- launch ----------------
extern "C" void kernel_launch(void* const* d_in, const int* in_sizes, int n_in,
                              void* d_out, int out_size){
    const int*   type_ids  = (const int*)  d_in[0];
    const int*   token_ids = (const int*)  d_in[1];
    const float* lw        = (const float*)d_in[4];
    const float* rw        = (const float*)d_in[5];
    const float* temb      = (const float*)d_in[7];
    const float* kemb      = (const float*)d_in[8];
    const float* WL        = (const float*)d_in[9];
    const float* WR        = (const float*)d_in[10];
    const float* WT        = (const float*)d_in[11];
    const float* bconv     = (const float*)d_in[12];
    const float* Wjm       = (const float*)d_in[13];
    float* out = (float*)d_out;

    k_embed<<<NN*32/256, 256>>>(type_ids, token_ids, temb, kemb);
    for (int l = 0; l < NLAY; l++)
        k_gemm<<<NPT/32, 256>>>(WL, WR, WT, bconv, lw, rw, l);
    k_top<<<NG, 1024>>>();
    for (int it = 0; it < 3; it++){
        k_phaseA<<<dim3(NG,4), 256>>>();
        k_phaseB<<<dim3(NG,4), 256>>>(it == 2 ? 1 : 0);
    }
    // round 0 (gamma uniform = 1/50)
    k_zsum2<<<dim3(NCLS,16), 512>>>(Wjm, 1);
    k_zfin<<<NG, 64>>>();
    k_dg<<<NPG, 512>>>(Wjm, 0);
    // round 1
    k_zsum2<<<dim3(NCLS,16), 512>>>(Wjm, 0);
    k_zfin<<<NG, 64>>>();
    k_dg<<<NPG, 512>>>(Wjm, 1);
    // round 2 (final)
    k_zsum2<<<dim3(NCLS,16), 512>>>(Wjm, 0);
    k_zfin<<<NG, 64>>>();
    k_logit<<<NG, 64>>>(out);
}

// round 7
// speedup vs baseline: 1.2647x; 1.2647x over previous
#include <cuda_runtime.h>
#include <cuda_bf16.h>
#include <cstdint>

#define NG   32
#define NPG  1024
#define NN   (NG*NPG)
#define HD   128
#define NLAY 4
#define NPAR 256
#define NPT  (NG*NPAR)
#define NCLS 50
#define DCCN 16
#define CS   (DCCN*NCLS)   // 800

typedef unsigned long long u64t;

__device__ __forceinline__ u64t pk2(float x, float y){ u64t r; asm("mov.b64 %0, {%1,%2};" : "=l"(r) : "f"(x), "f"(y)); return r; }
__device__ __forceinline__ void upk2(u64t p, float& x, float& y){ asm("mov.b64 {%0,%1}, %2;" : "=f"(x), "=f"(y) : "l"(p)); }
__device__ __forceinline__ u64t fma2_(u64t a, u64t b, u64t c){ u64t d; asm("fma.rn.f32x2 %0, %1, %2, %3;" : "=l"(d) : "l"(a), "l"(b), "l"(c)); return d; }
__device__ __forceinline__ u64t mul2_(u64t a, u64t b){ u64t d; asm("mul.rn.f32x2 %0, %1, %2;" : "=l"(d) : "l"(a), "l"(b)); return d; }
__device__ __forceinline__ u64t add2_(u64t a, u64t b){ u64t d; asm("add.rn.f32x2 %0, %1, %2;" : "=l"(d) : "l"(a), "l"(b)); return d; }

// ---------------- device scratch ----------------
__device__ __align__(256) float g_h0[NN*HD];
__device__ __align__(256) float g_f0[NN*HD];
__device__ __align__(256) float g_f1[NN*HD];
__device__ __align__(256) float g_f2[NN*HD];
__device__ __align__(256) float g_f3[NN*HD];
__device__ __align__(256) float g_l2[NN];
__device__ __align__(256) float g_u [NG*1024*4];
__device__ __align__(256) float g_Vc[NG*1024*4];
__device__ __align__(256) float g_m [NG*1024];   // NEGATED row max
__device__ __align__(256) float g_iZ[NG*1024];
__device__ __align__(256) float g_SC[NG*1024*4];
__device__ __align__(256) float g_delta[NN*NCLS];
__device__ __align__(256) float g_gamma[NN*NCLS];
__device__ __align__(256) float g_zs[NG*CS];
__device__ __align__(256) float g_z [NG*CS];

__device__ __forceinline__ float* featptr(int l){
    switch(l){ case 0: return g_f0; case 1: return g_f1; case 2: return g_f2; default: return g_f3; }
}

// ---------------- embedding + leaf l2 (leaf features stay in g_h0) ----------------
__global__ void k_embed(const int* __restrict__ type_ids, const int* __restrict__ token_ids,
                        const float* __restrict__ temb, const float* __restrict__ kemb){
    int idx = blockIdx.x*256 + threadIdx.x;          // n*32 + q  (warp == one node)
    int n = idx >> 5, q = idx & 31;
    float4 v;
    if (q < 16) v = *(const float4*)(temb + (size_t)type_ids[n]*64 + q*4);
    else        v = *(const float4*)(kemb + (size_t)token_ids[n]*64 + (q-16)*4);
    size_t o = (size_t)n*HD + q*4;
    *(float4*)(g_h0 + o) = v;
    bool leaf = (n & (NPG-1)) >= NPAR;
    float sq = v.x*v.x + v.y*v.y + v.z*v.z + v.w*v.w;
    #pragma unroll
    for (int s=16;s;s>>=1) sq += __shfl_xor_sync(0xffffffffu, sq, s);
    if (q == 0) g_l2[n] = leaf ? 4.f*sq : 0.f;
}

// ---------------- fused gather + GEMM + bias/relu + l2 ----------------
// 32-row tile, 256 threads, thread = 4 rows x 4 cols.
// Inner loop per (k,seg): 1 broadcast LDS.128 (A, 4 rows) + 1 LDS.128 (B = 2 native f32x2
// col-pairs) + 4 A-dup movs + 8 FFMA2.  grid = 256 blocks.
__global__ __launch_bounds__(256) void k_gemm(const float* __restrict__ WLp,
        const float* __restrict__ WRp, const float* __restrict__ WTp,
        const float* __restrict__ bconv,
        const float* __restrict__ lw, const float* __restrict__ rw, int layer){
    __shared__ __align__(16) float GLx[16][36];
    __shared__ __align__(16) float GRx[16][36];
    __shared__ __align__(16) float Xs [16][36];
    __shared__ __align__(16) float Ws3[3][16][128];
    __shared__ float lw_s[128], rw_s[128];
    const int tid = threadIdx.x;
    const int row0 = blockIdx.x*32;                  // parent row [0,8192)
    const int g = row0 >> 8, l0 = row0 & 255;
    const float* hin = (layer==0) ? g_h0 : featptr(layer-1);
    const float* Wb[3] = { WLp + layer*HD*HD, WRp + layer*HD*HD, WTp + layer*HD*HD };
    const int rgrp = tid >> 5;                       // 0..7 : rows rgrp*4 .. +3
    const int tx   = tid & 31;                       // cols tx*4 .. +3

    if (tid < 128){
        int e_local = 4*l0 + tid;
        bool valid = e_local < 1023;
        lw_s[tid] = valid ? lw[g*1023 + e_local] : 0.f;
        rw_s[tid] = valid ? rw[g*1023 + e_local] : 0.f;
    }

    u64t acc[4][2];                                  // [row r][colpair]
    #pragma unroll
    for (int r=0;r<4;r++){ acc[r][0]=0; acc[r][1]=0; }

    const int p_rel = tid >> 2, q = tid & 3;         // staging (tid<128)
    for (int k0 = 0; k0 < HD; k0 += 16){
        __syncthreads();
        if (tid < 128){
            // parent tile
            float4 v = *(const float4*)(hin + (size_t)(g*NPG + l0 + p_rel)*HD + k0 + q*4);
            Xs[q*4+0][p_rel]=v.x; Xs[q*4+1][p_rel]=v.y; Xs[q*4+2][p_rel]=v.z; Xs[q*4+3][p_rel]=v.w;
            // gathered child tiles (children >= NPAR are leaves: read h0)
            float glx=0,gly=0,glz=0,glw=0, grx=0,gry=0,grz=0,grw=0;
            #pragma unroll
            for (int j=0;j<4;j++){
                float wl = lw_s[p_rel*4+j], wr = rw_s[p_rel*4+j];
                int c_local = 4*(l0+p_rel) + 1 + j;
                if (c_local > 1023) c_local = 1023;  // weight already 0
                const float* csrc = (c_local < NPAR) ? hin : g_h0;
                float4 cv = *(const float4*)(csrc + (size_t)(g*NPG + c_local)*HD + k0 + q*4);
                glx += wl*cv.x; gly += wl*cv.y; glz += wl*cv.z; glw += wl*cv.w;
                grx += wr*cv.x; gry += wr*cv.y; grz += wr*cv.z; grw += wr*cv.w;
            }
            GLx[q*4+0][p_rel]=glx; GLx[q*4+1][p_rel]=gly; GLx[q*4+2][p_rel]=glz; GLx[q*4+3][p_rel]=glw;
            GRx[q*4+0][p_rel]=grx; GRx[q*4+1][p_rel]=gry; GRx[q*4+2][p_rel]=grz; GRx[q*4+3][p_rel]=grw;
        }
        // weight chunks for all 3 segments
        #pragma unroll
        for (int i=0;i<6;i++){
            int qq = tid + i*256;                    // 0..1535
            int seg = qq >> 9, r = qq & 511;
            int k = r >> 5, n4 = r & 31;
            *(float4*)&Ws3[seg][k][n4*4] = *(const float4*)(Wb[seg] + (size_t)(k0+k)*HD + n4*4);
        }
        __syncthreads();
        #pragma unroll 4
        for (int k=0;k<16;k++){
            #pragma unroll
            for (int seg=0;seg<3;seg++){
                const float* As = (seg==0) ? &GLx[k][0] : (seg==1) ? &GRx[k][0] : &Xs[k][0];
                float4 a = *(const float4*)&As[rgrp*4];                       // broadcast
                ulonglong2 w = *(const ulonglong2*)&Ws3[seg][k][tx*4];        // 2 native pairs
                u64t A0 = pk2(a.x,a.x), A1 = pk2(a.y,a.y), A2 = pk2(a.z,a.z), A3 = pk2(a.w,a.w);
                acc[0][0] = fma2_(A0, w.x, acc[0][0]);
                acc[0][1] = fma2_(A0, w.y, acc[0][1]);
                acc[1][0] = fma2_(A1, w.x, acc[1][0]);
                acc[1][1] = fma2_(A1, w.y, acc[1][1]);
                acc[2][0] = fma2_(A2, w.x, acc[2][0]);
                acc[2][1] = fma2_(A2, w.y, acc[2][1]);
                acc[3][0] = fma2_(A3, w.x, acc[3][0]);
                acc[3][1] = fma2_(A3, w.y, acc[3][1]);
            }
        }
    }
    // epilogue: bias + relu + store + per-row l2 (reduced over the 32 col-lanes)
    float* fo = featptr(layer);
    float4 bb = *(const float4*)(bconv + layer*HD + tx*4);
    float sqr[4];
    #pragma unroll
    for (int r=0;r<4;r++){
        float v[4];
        upk2(acc[r][0], v[0], v[1]);
        upk2(acc[r][1], v[2], v[3]);
        v[0] = fmaxf(v[0]+bb.x, 0.f); v[1] = fmaxf(v[1]+bb.y, 0.f);
        v[2] = fmaxf(v[2]+bb.z, 0.f); v[3] = fmaxf(v[3]+bb.w, 0.f);
        sqr[r] = v[0]*v[0] + v[1]*v[1] + v[2]*v[2] + v[3]*v[3];
        int loc = l0 + rgrp*4 + r;
        float4 o = {v[0],v[1],v[2],v[3]};
        *(float4*)(fo + (size_t)(g*NPG + loc)*HD + tx*4) = o;
    }
    #pragma unroll
    for (int o=16;o;o>>=1){
        sqr[0] += __shfl_xor_sync(0xffffffffu, sqr[0], o);
        sqr[1] += __shfl_xor_sync(0xffffffffu, sqr[1], o);
        sqr[2] += __shfl_xor_sync(0xffffffffu, sqr[2], o);
        sqr[3] += __shfl_xor_sync(0xffffffffu, sqr[3], o);
    }
    if (tx < 4) atomicAdd(&g_l2[g*NPG + l0 + rgrp*4 + tx], sqr[tx]);
}

// ---------------- top-8 per graph + gather u, init Vcum ----------------
__global__ __launch_bounds__(1024) void k_top(){
    __shared__ float l2s[1024];
    __shared__ float rv[32]; __shared__ int ri[32];
    __shared__ int top8[8];
    int g = blockIdx.x, tid = threadIdx.x;
    int lane = tid & 31, warp = tid >> 5;
    l2s[tid] = g_l2[g*1024 + tid];
    __syncthreads();
    for (int t=0;t<8;t++){
        float v = l2s[tid]; int idx = tid;
        #pragma unroll
        for (int o=16;o;o>>=1){
            float v2 = __shfl_xor_sync(0xffffffffu, v, o);
            int   i2 = __shfl_xor_sync(0xffffffffu, idx, o);
            if (v2 > v || (v2 == v && i2 < idx)){ v = v2; idx = i2; }
        }
        if (lane == 0){ rv[warp] = v; ri[warp] = idx; }
        __syncthreads();
        if (warp == 0){
            float vv = rv[lane]; int ii = ri[lane];
            #pragma unroll
            for (int o=16;o;o>>=1){
                float v2 = __shfl_xor_sync(0xffffffffu, vv, o);
                int   i2 = __shfl_xor_sync(0xffffffffu, ii, o);
                if (v2 > vv || (v2 == vv && i2 < ii)){ vv = v2; ii = i2; }
            }
            if (lane == 0){ top8[t] = ii; l2s[ii] = -1e30f; }
        }
        __syncthreads();
    }
    int bcap = tid >> 7, hh = tid & 127;
    int node = top8[bcap];
    size_t nb = (size_t)(g*NPG + node)*HD + hh;
    float4 uv;
    if (node < NPAR){
        uv.x = g_f0[nb]; uv.y = g_f1[nb]; uv.z = g_f2[nb]; uv.w = g_f3[nb];
    } else {
        float h = g_h0[nb];
        uv.x = h; uv.y = h; uv.z = h; uv.w = h;
    }
    *(float4*)&g_u [(size_t)(g*1024 + tid)*4] = uv;
    *(float4*)&g_Vc[(size_t)(g*1024 + tid)*4] = uv;
}

// ---------------- VTS phase A: per-row (neg)max + 1/Z, ILP-2, 128 thr ----------------
__global__ __launch_bounds__(128) void k_phaseA(){
    __shared__ __align__(16) ulonglong2 sVp2[1024];
    int g = blockIdx.x, tid = threadIdx.x;
    int row = blockIdx.y*128 + tid;
    for (int i=tid;i<512;i+=128){
        float4 c0 = *(const float4*)&g_Vc[(size_t)(g*1024 + 2*i  )*4];
        float4 c1 = *(const float4*)&g_Vc[(size_t)(g*1024 + 2*i+1)*4];
        ulonglong2 A, B;
        A.x = pk2(c0.x,c1.x); A.y = pk2(c0.y,c1.y);
        B.x = pk2(c0.z,c1.z); B.y = pk2(c0.w,c1.w);
        sVp2[i*2] = A; sVp2[i*2+1] = B;
    }
    __syncthreads();
    float4 u = *(const float4*)&g_u[(size_t)(g*1024 + row)*4];
    u64t U0 = pk2(u.x,u.x), U1 = pk2(u.y,u.y), U2 = pk2(u.z,u.z), U3 = pk2(u.w,u.w);
    float ma = -1e30f, mb = -1e30f;
    #pragma unroll 2
    for (int jp=0;jp<512;jp+=2){
        ulonglong2 P01 = sVp2[jp*2],   P23 = sVp2[jp*2+1];
        ulonglong2 Q01 = sVp2[jp*2+2], Q23 = sVp2[jp*2+3];
        u64t t = mul2_(U0, P01.x); u64t s = mul2_(U0, Q01.x);
        t = fma2_(U1, P01.y, t);   s = fma2_(U1, Q01.y, s);
        t = fma2_(U2, P23.x, t);   s = fma2_(U2, Q23.x, s);
        t = fma2_(U3, P23.y, t);   s = fma2_(U3, Q23.y, s);
        float t0,t1,s0,s1; upk2(t,t0,t1); upk2(s,s0,s1);
        ma = fmaxf(ma, fmaxf(t0,t1));
        mb = fmaxf(mb, fmaxf(s0,s1));
    }
    float mn = -fmaxf(ma, mb);
    u64t MN = pk2(mn, mn);
    float za = 0.f, zb = 0.f;
    #pragma unroll 2
    for (int jp=0;jp<512;jp+=2){
        ulonglong2 P01 = sVp2[jp*2],   P23 = sVp2[jp*2+1];
        ulonglong2 Q01 = sVp2[jp*2+2], Q23 = sVp2[jp*2+3];
        u64t t = mul2_(U0, P01.x); u64t s = mul2_(U0, Q01.x);
        t = fma2_(U1, P01.y, t);   s = fma2_(U1, Q01.y, s);
        t = fma2_(U2, P23.x, t);   s = fma2_(U2, Q23.x, s);
        t = fma2_(U3, P23.y, t);   s = fma2_(U3, Q23.y, s);
        t = add2_(t, MN);          s = add2_(s, MN);
        float t0,t1,s0,s1; upk2(t,t0,t1); upk2(s,s0,s1);
        za += __expf(t0); za += __expf(t1);
        zb += __expf(s0); zb += __expf(s1);
    }
    g_m [g*1024 + row] = mn;
    g_iZ[g*1024 + row] = 1.f/(za+zb);
}

// ---------------- VTS phase B: v_new = beta^T u, ILP-2, 128 thr ----------------
__global__ __launch_bounds__(128) void k_phaseB(int last){
    __shared__ __align__(16) ulonglong2 sUp2[1024];
    __shared__ __align__(16) float4 sUn[1024];
    __shared__ u64t sMn2[512];
    __shared__ u64t sZ2[512];
    int g = blockIdx.x, tid = threadIdx.x;
    int col = blockIdx.y*128 + tid;
    for (int i=tid;i<512;i+=128){
        float4 u0 = *(const float4*)&g_u[(size_t)(g*1024 + 2*i  )*4];
        float4 u1 = *(const float4*)&g_u[(size_t)(g*1024 + 2*i+1)*4];
        sUn[2*i] = u0; sUn[2*i+1] = u1;
        ulonglong2 A, B;
        A.x = pk2(u0.x,u1.x); A.y = pk2(u0.y,u1.y);
        B.x = pk2(u0.z,u1.z); B.y = pk2(u0.w,u1.w);
        sUp2[i*2] = A; sUp2[i*2+1] = B;
        sMn2[i] = pk2(g_m [g*1024+2*i], g_m [g*1024+2*i+1]);
        sZ2 [i] = pk2(g_iZ[g*1024+2*i], g_iZ[g*1024+2*i+1]);
    }
    __syncthreads();
    float4 c = *(const float4*)&g_Vc[(size_t)(g*1024 + col)*4];
    u64t C0 = pk2(c.x,c.x), C1 = pk2(c.y,c.y), C2 = pk2(c.z,c.z), C3 = pk2(c.w,c.w);
    u64t a01a = 0, a23a = 0, a01b = 0, a23b = 0;
    #pragma unroll 2
    for (int ip=0;ip<512;ip+=2){
        ulonglong2 P01 = sUp2[ip*2],   P23 = sUp2[ip*2+1];
        ulonglong2 Q01 = sUp2[ip*2+2], Q23 = sUp2[ip*2+3];
        u64t t = mul2_(C0, P01.x);  u64t s2 = mul2_(C0, Q01.x);
        t = fma2_(C1, P01.y, t);    s2 = fma2_(C1, Q01.y, s2);
        t = fma2_(C2, P23.x, t);    s2 = fma2_(C2, Q23.x, s2);
        t = fma2_(C3, P23.y, t);    s2 = fma2_(C3, Q23.y, s2);
        t = add2_(t, sMn2[ip]);     s2 = add2_(s2, sMn2[ip+1]);
        float t0,t1,s0,s1; upk2(t,t0,t1); upk2(s2,s0,s1);
        float e0 = __expf(t0), e1 = __expf(t1);
        float f0 = __expf(s0), f1 = __expf(s1);
        u64t wza = mul2_(pk2(e0,e1), sZ2[ip]);
        u64t wzb = mul2_(pk2(f0,f1), sZ2[ip+1]);
        float w0,w1,x0,x1; upk2(wza,w0,w1); upk2(wzb,x0,x1);
        u64t W0 = pk2(w0,w0), W1 = pk2(w1,w1);
        u64t X0 = pk2(x0,x0), X1 = pk2(x1,x1);
        ulonglong2 Ua = *(const ulonglong2*)&sUn[2*ip];
        ulonglong2 Ub = *(const ulonglong2*)&sUn[2*ip+1];
        ulonglong2 Uc = *(const ulonglong2*)&sUn[2*ip+2];
        ulonglong2 Ud = *(const ulonglong2*)&sUn[2*ip+3];
        a01a = fma2_(W0, Ua.x, a01a); a23a = fma2_(W0, Ua.y, a23a);
        a01a = fma2_(W1, Ub.x, a01a); a23a = fma2_(W1, Ub.y, a23a);
        a01b = fma2_(X0, Uc.x, a01b); a23b = fma2_(X0, Uc.y, a23b);
        a01b = fma2_(X1, Ud.x, a01b); a23b = fma2_(X1, Ud.y, a23b);
    }
    u64t a01 = add2_(a01a, a01b), a23 = add2_(a23a, a23b);
    float a0,a1,a2,a3;
    upk2(a01, a0, a1); upk2(a23, a2, a3);
    if (!last){
        float4 o; o.x=c.x+a0; o.y=c.y+a1; o.z=c.z+a2; o.w=c.w+a3;
        *(float4*)&g_Vc[(size_t)(g*1024 + col)*4] = o;
    } else {
        float sq = a0*a0 + a1*a1 + a2*a2 + a3*a3;
        float sc = sq/(1.f+sq)/(sqrtf(sq + 1e-10f) + 1e-8f);
        float4 o; o.x=a0*sc; o.y=a1*sc; o.z=a2*sc; o.w=a3*sc;
        *(float4*)&g_SC[(size_t)(g*1024 + col)*4] = o;
    }
}

// ---------------- zsum[b,c,s] = sum_{n,m} Wjm[n,c,s,m] * gamma[b,n,s]*SC[b,n,m] ----------------
__global__ __launch_bounds__(512) void k_zsum2(const float* __restrict__ Wjm, int round0){
    __shared__ __align__(16) float4 Ws4[64*16];   // [n][c]
    __shared__ __align__(16) float4 Xs4[64*32];   // [n][b]
    int s = blockIdx.x;
    int n0 = blockIdx.y*64;
    int tid = threadIdx.x;
    const float4* W4 = (const float4*)Wjm;
    #pragma unroll
    for (int i = tid; i < 1024; i += 512){
        int n = i >> 4, c = i & 15;
        Ws4[i] = W4[(size_t)(n0+n)*800 + c*50 + s];
    }
    #pragma unroll
    for (int i = tid; i < 2048; i += 512){
        int n = i >> 5, b = i & 31;
        float ga = round0 ? 0.02f : g_gamma[(size_t)(b*1024 + n0 + n)*50 + s];
        float4 sc = *(const float4*)&g_SC[(size_t)(b*1024 + n0 + n)*4];
        float4 x; x.x = ga*sc.x; x.y = ga*sc.y; x.z = ga*sc.z; x.w = ga*sc.w;
        Xs4[n*32 + b] = x;
    }
    __syncthreads();
    int c = tid & 15, b = tid >> 4;
    float acc = 0.f;
    #pragma unroll 8
    for (int n = 0; n < 64; n++){
        float4 w = Ws4[n*16 + c];
        float4 x = Xs4[n*32 + b];
        acc += w.x*x.x + w.y*x.y + w.z*x.z + w.w*x.w;
    }
    atomicAdd(&g_zs[b*CS + c*NCLS + s], acc);
}

// ---------------- z = squash_c(zsum); re-zero zs for next round ----------------
__global__ void k_zfin(){
    int b = blockIdx.x, s = threadIdx.x;
    if (s >= NCLS) return;
    float vals[DCCN]; float sq = 0.f;
    #pragma unroll
    for (int c=0;c<DCCN;c++){
        float v = g_zs[b*CS + c*NCLS + s]; vals[c]=v; sq += v*v;
        g_zs[b*CS + c*NCLS + s] = 0.f;
    }
    float sc = sq/(1.f+sq)/(sqrtf(sq + 1e-10f) + 1e-8f);
    #pragma unroll
    for (int c=0;c<DCCN;c++) g_z[b*CS + c*NCLS + s] = vals[c]*sc;
}

// ---------------- fused: delta update + gamma = softmax_s(delta) ----------------
__global__ __launch_bounds__(512) void k_dg(const float* __restrict__ Wjm, int accum){
    __shared__ __align__(16) float4 Ws4[800];
    __shared__ float sdel[1600];
    __shared__ float smx[32], siz[32];
    int n = blockIdx.x;
    int tid = threadIdx.x;
    const float4* W4 = (const float4*)Wjm + (size_t)n*800;
    for (int i = tid; i < 800; i += 512) Ws4[i] = W4[i];
    __syncthreads();
    for (int p = tid; p < 1600; p += 512){
        int b = p / 50, s = p % 50;
        float tx=0.f, ty=0.f, tz=0.f, tw=0.f;
        #pragma unroll
        for (int c = 0; c < 16; c++){
            float zv = g_z[b*CS + c*NCLS + s];
            float4 w = Ws4[c*50 + s];
            tx += w.x*zv; ty += w.y*zv; tz += w.z*zv; tw += w.w*zv;
        }
        float4 sc = *(const float4*)&g_SC[(size_t)(b*1024 + n)*4];
        float d = tx*sc.x + ty*sc.y + tz*sc.z + tw*sc.w;
        size_t o = (size_t)(b*1024 + n)*50 + s;
        if (accum) d += g_delta[o];
        g_delta[o] = d;
        sdel[p] = d;
    }
    __syncthreads();
    if (tid < 32){
        float m = -1e30f;
        for (int k=0;k<NCLS;k++) m = fmaxf(m, sdel[tid*50 + k]);
        float Z = 0.f;
        for (int k=0;k<NCLS;k++) Z += __expf(sdel[tid*50 + k] - m);
        smx[tid] = m; siz[tid] = 1.f/Z;
    }
    __syncthreads();
    for (int p = tid; p < 1600; p += 512){
        int b = p / 50;
        size_t o = (size_t)(b*1024 + n)*50 + (p % 50);
        g_gamma[o] = __expf(sdel[p] - smx[b]) * siz[b];
    }
}

// ---------------- logits ----------------
__global__ void k_logit(float* __restrict__ out){
    int b = blockIdx.x, s = threadIdx.x;
    if (s >= NCLS) return;
    float sq = 0.f;
    #pragma unroll
    for (int c=0;c<DCCN;c++){ float v = g_z[b*CS + c*NCLS + s]; sq += v*v; }
    float lg = sqrtf(sq + 1e-10f);
    out[b*NCLS + s] = lg;
    out[NG*NCLS + b*NCLS + s] = lg;
}

// ---------------- launch ----------------
extern "C" void kernel_launch(void* const* d_in, const int* in_sizes, int n_in,
                              void* d_out, int out_size){
    const int*   type_ids  = (const int*)  d_in[0];
    const int*   token_ids = (const int*)  d_in[1];
    const float* lw        = (const float*)d_in[4];
    const float* rw        = (const float*)d_in[5];
    const float* temb      = (const float*)d_in[7];
    const float* kemb      = (const float*)d_in[8];
    const float* WL        = (const float*)d_in[9];
    const float* WR        = (const float*)d_in[10];
    const float* WT        = (const float*)d_in[11];
    const float* bconv     = (const float*)d_in[12];
    const float* Wjm       = (const float*)d_in[13];
    float* out = (float*)d_out;

    k_embed<<<NN*32/256, 256>>>(type_ids, token_ids, temb, kemb);
    for (int l = 0; l < NLAY; l++)
        k_gemm<<<NPT/32, 256>>>(WL, WR, WT, bconv, lw, rw, l);
    k_top<<<NG, 1024>>>();
    for (int it = 0; it < 3; it++){
        k_phaseA<<<dim3(NG,8), 128>>>();
        k_phaseB<<<dim3(NG,8), 128>>>(it == 2 ? 1 : 0);
    }
    // round 0 (gamma uniform = 1/50)
    k_zsum2<<<dim3(NCLS,16), 512>>>(Wjm, 1);
    k_zfin<<<NG, 64>>>();
    k_dg<<<NPG, 512>>>(Wjm, 0);
    // round 1
    k_zsum2<<<dim3(NCLS,16), 512>>>(Wjm, 0);
    k_zfin<<<NG, 64>>>();
    k_dg<<<NPG, 512>>>(Wjm, 1);
    // round 2 (final)
    k_zsum2<<<dim3(NCLS,16), 512>>>(Wjm, 0);
    k_zfin<<<NG, 64>>>();
    k_logit<<<NG, 64>>>(out);
}